// round 16
// baseline (speedup 1.0000x reference)
#include <cuda_runtime.h>
#include <cuda_bf16.h>
#include <cuda_fp16.h>
#include <cstdint>

#define MAXN 100000
#define MAXE 1600000
#define DIMV 128
#define SCAN_B 1024
#define MAXL 8
#define MAXV 4096
#define ASTH 136           // padded smem stride in halves
#define ASTB 272           // padded smem stride in bytes
#define RD_SLOTS 16

// ---------------- scratch (device globals; no allocation allowed) -------------
__device__ __align__(256) __half g_hf[MAXN * DIMV];         // node features (fp16)
__device__ __align__(256) __half g_hw[MAXN * DIMV];         // h @ W (fp16, unscaled)
__device__ __align__(256) __half g_wt[MAXL * DIMV * DIMV];  // W^T per layer (fp16)
__device__ __align__(256) __half g_embh[MAXV * DIMV];       // fp16 embedding table
__device__ int    g_csr[MAXE];
__device__ int    g_row_ptr[MAXN + 1];
__device__ int    g_cursor[MAXN];
__device__ int    g_cnt_src[MAXN];
__device__ int    g_cnt_dst[MAXN];
__device__ float  g_norm_src[MAXN];
__device__ float  g_norm_dst[MAXN];
__device__ int    g_spine[128];

// ---------------- side stream + events (created at load, before baseline) -----
struct StreamInit {
    cudaStream_t s2;
    cudaEvent_t evA, evC;
    StreamInit() {
        cudaStreamCreateWithFlags(&s2, cudaStreamNonBlocking);
        cudaEventCreateWithFlags(&evA, cudaEventDisableTiming);
        cudaEventCreateWithFlags(&evC, cudaEventDisableTiming);
    }
};
static StreamInit g_si;

// ---------------- PTX helpers (base-PTX: ldmatrix/stmatrix/mma/cp.async) ------
__device__ __forceinline__ uint32_t smem_u32(const void* p) {
    uint32_t a;
    asm("{ .reg .u64 t; cvta.to.shared.u64 t, %1; cvt.u32.u64 %0, t; }" : "=r"(a) : "l"(p));
    return a;
}
__device__ __forceinline__ void ldsm_x4(uint32_t& r0, uint32_t& r1, uint32_t& r2,
                                        uint32_t& r3, uint32_t addr) {
    asm volatile("ldmatrix.sync.aligned.m8n8.x4.shared.b16 {%0,%1,%2,%3}, [%4];"
                 : "=r"(r0), "=r"(r1), "=r"(r2), "=r"(r3) : "r"(addr));
}
__device__ __forceinline__ void stsm_x4(uint32_t addr, uint32_t r0, uint32_t r1,
                                        uint32_t r2, uint32_t r3) {
    asm volatile("stmatrix.sync.aligned.m8n8.x4.shared.b16 [%0], {%1,%2,%3,%4};"
                 :: "r"(addr), "r"(r0), "r"(r1), "r"(r2), "r"(r3) : "memory");
}
__device__ __forceinline__ void mma16816(float* c, uint32_t a0, uint32_t a1,
                                         uint32_t a2, uint32_t a3,
                                         uint32_t b0, uint32_t b1) {
    asm volatile("mma.sync.aligned.m16n8k16.row.col.f32.f16.f16.f32 "
                 "{%0,%1,%2,%3}, {%4,%5,%6,%7}, {%8,%9}, {%0,%1,%2,%3};"
                 : "+f"(c[0]), "+f"(c[1]), "+f"(c[2]), "+f"(c[3])
                 : "r"(a0), "r"(a1), "r"(a2), "r"(a3), "r"(b0), "r"(b1));
}
__device__ __forceinline__ void cp16(uint32_t daddr, const void* gaddr, int srcbytes) {
    asm volatile("cp.async.cg.shared.global [%0], [%1], 16, %2;"
                 :: "r"(daddr), "l"(gaddr), "r"(srcbytes) : "memory");
}
__device__ __forceinline__ void cp_commit() {
    asm volatile("cp.async.commit_group;" ::: "memory");
}
__device__ __forceinline__ void cp_wait0() {
    asm volatile("cp.async.wait_group 0;" ::: "memory");
}

// ---------------- s2 head: zero counters (tiny, unblocks hist ASAP) -----------
__global__ void k_zero_counts(int n) {
    int i = blockIdx.x * blockDim.x + threadIdx.x;
    if (i < n) { g_cnt_src[i] = 0; g_cnt_dst[i] = 0; }
}

// ---------------- main prep: W^T + emb->fp16 + zero out -----------------------
__global__ void k_prep2(const float* __restrict__ W, const float* __restrict__ emb,
                        int layers, int nbOut, float* __restrict__ out, int out_n,
                        int vocab) {
    int b = blockIdx.x;
    if (b < layers) {
        const float* Wl = W + (size_t)b * DIMV * DIMV;
        __half* Wt = g_wt + (size_t)b * DIMV * DIMV;
        for (int i = threadIdx.x; i < DIMV * DIMV; i += 256) {
            int nr = i >> 7, k = i & 127;
            Wt[nr * DIMV + k] = __float2half(Wl[k * DIMV + nr]);
        }
    } else if (b < layers + nbOut) {
        int i = (b - layers) * 256 + threadIdx.x;
        if (i < out_n) out[i] = 0.0f;
    } else {
        int idx = (b - layers - nbOut) * 256 + threadIdx.x;
        if (idx < vocab * 32) {
            float4 a = reinterpret_cast<const float4*>(emb)[idx];
            __half2 h0 = __floats2half2_rn(a.x, a.y);
            __half2 h1 = __floats2half2_rn(a.z, a.w);
            uint2 v;
            v.x = *reinterpret_cast<uint32_t*>(&h0);
            v.y = *reinterpret_cast<uint32_t*>(&h1);
            reinterpret_cast<uint2*>(g_embh)[idx] = v;
        }
    }
}

// ---------------- degree histograms (4 edges/thread) --------------------------
__global__ void k_hist(const int* __restrict__ src, const int* __restrict__ dst, int E) {
    int q = blockIdx.x * blockDim.x + threadIdx.x;
    int e0 = q * 4;
    if (e0 + 3 < E) {
        int4 s = *reinterpret_cast<const int4*>(src + e0);
        int4 d = *reinterpret_cast<const int4*>(dst + e0);
        atomicAdd(&g_cnt_src[s.x], 1); atomicAdd(&g_cnt_src[s.y], 1);
        atomicAdd(&g_cnt_src[s.z], 1); atomicAdd(&g_cnt_src[s.w], 1);
        atomicAdd(&g_cnt_dst[d.x], 1); atomicAdd(&g_cnt_dst[d.y], 1);
        atomicAdd(&g_cnt_dst[d.z], 1); atomicAdd(&g_cnt_dst[d.w], 1);
    } else {
        for (int e = e0; e < E; ++e) {
            atomicAdd(&g_cnt_src[src[e]], 1);
            atomicAdd(&g_cnt_dst[dst[e]], 1);
        }
    }
}

// ---------------- scanA: per-block exclusive scan + spine + norms -------------
__global__ void k_scanA(int n) {
    __shared__ int s[SCAN_B];
    int i = blockIdx.x * SCAN_B + threadIdx.x;
    int v = (i < n) ? g_cnt_dst[i] : 0;
    if (i < n) {
        g_norm_dst[i] = rsqrtf((float)max(v, 1));
        g_norm_src[i] = rsqrtf((float)max(g_cnt_src[i], 1));
    }
    s[threadIdx.x] = v;
    __syncthreads();
    for (int off = 1; off < SCAN_B; off <<= 1) {
        int t = (threadIdx.x >= off) ? s[threadIdx.x - off] : 0;
        __syncthreads();
        s[threadIdx.x] += t;
        __syncthreads();
    }
    if (i < n) g_row_ptr[i] = s[threadIdx.x] - v;   // exclusive within block
    if (threadIdx.x == SCAN_B - 1) g_spine[blockIdx.x] = s[SCAN_B - 1];
}

// ---------------- scanB: add spine prefix, finalize row_ptr + cursor ----------
// Each block reduces spine[0..bid) itself (<=128 entries) — replaces scan2+scan3.
__global__ void __launch_bounds__(256) k_scanB(int n, int E) {
    __shared__ int red[256];
    int b = blockIdx.x;
    int t = threadIdx.x;

    int partial = 0;
    for (int i = t; i < b; i += 256) partial += g_spine[i];
    red[t] = partial;
    __syncthreads();
    for (int off = 128; off > 0; off >>= 1) {
        if (t < off) red[t] += red[t + off];
        __syncthreads();
    }
    int prefix = red[0];

    for (int i = b * SCAN_B + t; i < min(n, (b + 1) * SCAN_B); i += 256) {
        int r = g_row_ptr[i] + prefix;
        g_row_ptr[i] = r;
        g_cursor[i]  = r;
    }
    if (b == 0 && t == 0) g_row_ptr[n] = E;
}

// ---------------- CSR fill (counting sort by dst, 4 edges/thread) -------------
__global__ void k_fill(const int* __restrict__ src, const int* __restrict__ dst, int E) {
    int q = blockIdx.x * blockDim.x + threadIdx.x;
    int e0 = q * 4;
    if (e0 + 3 < E) {
        int4 s = *reinterpret_cast<const int4*>(src + e0);
        int4 d = *reinterpret_cast<const int4*>(dst + e0);
        g_csr[atomicAdd(&g_cursor[d.x], 1)] = s.x;
        g_csr[atomicAdd(&g_cursor[d.y], 1)] = s.y;
        g_csr[atomicAdd(&g_cursor[d.z], 1)] = s.z;
        g_csr[atomicAdd(&g_cursor[d.w], 1)] = s.w;
    } else {
        for (int e = e0; e < E; ++e)
            g_csr[atomicAdd(&g_cursor[dst[e]], 1)] = src[e];
    }
}

// ---------------- HMMA GEMM, M=64 tile, 128 threads, 4 blocks/SM --------------
// hw = h @ W (UNSCALED — norm_src applied in agg). GATHER_EMB=1: layer 0.
#define SMO_AB 17408
#define SM_G64 52224

template <int GATHER_EMB>
__global__ void __launch_bounds__(128) k_gemm64(const __half* __restrict__ Wt,
                                                const int* __restrict__ feat_id,
                                                int n) {
    extern __shared__ char sm[];
    uint32_t sAu = smem_u32(sm);
    uint32_t sBu = sAu + SMO_AB;
    char* sA = sm;
    int tid = threadIdx.x, warp = tid >> 5, lane = tid & 31;
    int row0 = blockIdx.x * 64;
    if (row0 >= n) return;

    const uint4* Asrc = GATHER_EMB ? reinterpret_cast<const uint4*>(g_embh)
                                   : reinterpret_cast<const uint4*>(g_hf);
    const uint4* Bsrc = reinterpret_cast<const uint4*>(Wt);

    for (int i = tid; i < 2048; i += 128) {
        int r = i >> 4, c = i & 15;
        cp16(sBu + r * ASTB + c * 16, Bsrc + i, 16);
    }
    for (int i = tid; i < 1024; i += 128) {
        int r = i >> 4, c = i & 15;
        int gr = row0 + r;
        int ok = (gr < n) ? 16 : 0;
        size_t srow;
        if (GATHER_EMB) srow = (gr < n) ? (size_t)feat_id[gr] : 0;
        else            srow = (gr < n) ? (size_t)gr : 0;
        cp16(sAu + r * ASTB + c * 16, Asrc + (srow * 16 + c), ok);
    }
    cp_commit();
    cp_wait0();
    __syncthreads();

    int wm = warp >> 1, wn = warp & 1;
    int m0 = wm * 32, nn0 = wn * 64;

    uint32_t a_base = sAu + (m0 + (lane & 7) + ((lane & 8) ? 8 : 0)) * ASTB
                          + ((lane & 16) ? 16 : 0);
    uint32_t b_base = sBu + (nn0 + (lane & 7) + ((lane & 16) ? 8 : 0)) * ASTB
                          + ((lane & 8) ? 16 : 0);

    float acc[2][8][4];
#pragma unroll
    for (int mt = 0; mt < 2; mt++)
#pragma unroll
        for (int j = 0; j < 8; j++)
#pragma unroll
            for (int q = 0; q < 4; q++) acc[mt][j][q] = 0.f;

#pragma unroll
    for (int ks = 0; ks < 8; ks++) {
        uint32_t a[2][4];
#pragma unroll
        for (int mt = 0; mt < 2; mt++)
            ldsm_x4(a[mt][0], a[mt][1], a[mt][2], a[mt][3],
                    a_base + mt * 16 * ASTB + ks * 32);
#pragma unroll
        for (int jj = 0; jj < 4; jj++) {
            uint32_t b0, b1, b2, b3;
            ldsm_x4(b0, b1, b2, b3, b_base + jj * 16 * ASTB + ks * 32);
#pragma unroll
            for (int mt = 0; mt < 2; mt++) {
                mma16816(acc[mt][2 * jj],     a[mt][0], a[mt][1], a[mt][2], a[mt][3], b0, b1);
                mma16816(acc[mt][2 * jj + 1], a[mt][0], a[mt][1], a[mt][2], a[mt][3], b2, b3);
            }
        }
    }
    __syncthreads();

#pragma unroll
    for (int mt = 0; mt < 2; mt++) {
        uint32_t st_base = sAu
            + (m0 + mt * 16 + (lane & 7) + ((lane & 8) ? 8 : 0)) * ASTB
            + nn0 * 2 + ((lane & 16) ? 16 : 0);
#pragma unroll
        for (int jj = 0; jj < 4; jj++) {
            __half2 t0lo = __floats2half2_rn(acc[mt][2*jj][0],   acc[mt][2*jj][1]);
            __half2 t0hi = __floats2half2_rn(acc[mt][2*jj][2],   acc[mt][2*jj][3]);
            __half2 t1lo = __floats2half2_rn(acc[mt][2*jj+1][0], acc[mt][2*jj+1][1]);
            __half2 t1hi = __floats2half2_rn(acc[mt][2*jj+1][2], acc[mt][2*jj+1][3]);
            stsm_x4(st_base + jj * 32,
                    *reinterpret_cast<uint32_t*>(&t0lo),
                    *reinterpret_cast<uint32_t*>(&t0hi),
                    *reinterpret_cast<uint32_t*>(&t1lo),
                    *reinterpret_cast<uint32_t*>(&t1hi));
        }
    }
    __syncthreads();

    for (int i = tid; i < 1024; i += 128) {
        int r = i >> 4, c = i & 15;
        int gr = row0 + r;
        if (gr < n)
            reinterpret_cast<uint4*>(g_hw)[(size_t)gr * 16 + c] =
                *reinterpret_cast<uint4*>(sA + r * ASTB + c * 16);
    }
}

// ---------------- edge aggregation: h = relu(nd ⊙ Σ ns[s]·hw[s] + b) ---------
__global__ void __launch_bounds__(256) k_agg(const float* __restrict__ bias, int n) {
    int gw   = (blockIdx.x * blockDim.x + threadIdx.x) >> 5;
    int lane = threadIdx.x & 31;
    int node = gw * 2 + (lane >> 4);
    int l16  = lane & 15;
    if (node >= n) return;

    int beg = g_row_ptr[node];
    int end = g_row_ptr[node + 1];

    const uint4* hw4 = reinterpret_cast<const uint4*>(g_hw);
    float a0 = 0.f, a1 = 0.f, a2 = 0.f, a3 = 0.f;
    float a4 = 0.f, a5 = 0.f, a6 = 0.f, a7 = 0.f;

    int e = beg;
    for (; e + 7 < end; e += 8) {
        int s[8];
#pragma unroll
        for (int j = 0; j < 8; j++) s[j] = g_csr[e + j];
        float nsv[8];
        uint4 v[8];
#pragma unroll
        for (int j = 0; j < 8; j++) { nsv[j] = g_norm_src[s[j]];
                                      v[j] = hw4[(size_t)s[j] * 16 + l16]; }
#pragma unroll
        for (int j = 0; j < 8; j++) {
            float2 f0 = __half22float2(*reinterpret_cast<__half2*>(&v[j].x));
            float2 f1 = __half22float2(*reinterpret_cast<__half2*>(&v[j].y));
            float2 f2 = __half22float2(*reinterpret_cast<__half2*>(&v[j].z));
            float2 f3 = __half22float2(*reinterpret_cast<__half2*>(&v[j].w));
            float ns = nsv[j];
            a0 = fmaf(f0.x, ns, a0); a1 = fmaf(f0.y, ns, a1);
            a2 = fmaf(f1.x, ns, a2); a3 = fmaf(f1.y, ns, a3);
            a4 = fmaf(f2.x, ns, a4); a5 = fmaf(f2.y, ns, a5);
            a6 = fmaf(f3.x, ns, a6); a7 = fmaf(f3.y, ns, a7);
        }
    }
    for (; e < end; ++e) {
        int s = g_csr[e];
        float ns = g_norm_src[s];
        uint4 v = hw4[(size_t)s * 16 + l16];
        float2 f0 = __half22float2(*reinterpret_cast<__half2*>(&v.x));
        float2 f1 = __half22float2(*reinterpret_cast<__half2*>(&v.y));
        float2 f2 = __half22float2(*reinterpret_cast<__half2*>(&v.z));
        float2 f3 = __half22float2(*reinterpret_cast<__half2*>(&v.w));
        a0 = fmaf(f0.x, ns, a0); a1 = fmaf(f0.y, ns, a1);
        a2 = fmaf(f1.x, ns, a2); a3 = fmaf(f1.y, ns, a3);
        a4 = fmaf(f2.x, ns, a4); a5 = fmaf(f2.y, ns, a5);
        a6 = fmaf(f3.x, ns, a6); a7 = fmaf(f3.y, ns, a7);
    }

    float nd = g_norm_dst[node];
    float4 bb0 = reinterpret_cast<const float4*>(bias)[l16 * 2];
    float4 bb1 = reinterpret_cast<const float4*>(bias)[l16 * 2 + 1];
    __half2 p0 = __floats2half2_rn(fmaxf(fmaf(a0, nd, bb0.x), 0.f),
                                   fmaxf(fmaf(a1, nd, bb0.y), 0.f));
    __half2 p1 = __floats2half2_rn(fmaxf(fmaf(a2, nd, bb0.z), 0.f),
                                   fmaxf(fmaf(a3, nd, bb0.w), 0.f));
    __half2 p2 = __floats2half2_rn(fmaxf(fmaf(a4, nd, bb1.x), 0.f),
                                   fmaxf(fmaf(a5, nd, bb1.y), 0.f));
    __half2 p3 = __floats2half2_rn(fmaxf(fmaf(a6, nd, bb1.z), 0.f),
                                   fmaxf(fmaf(a7, nd, bb1.w), 0.f));
    uint4 o;
    o.x = *reinterpret_cast<uint32_t*>(&p0);
    o.y = *reinterpret_cast<uint32_t*>(&p1);
    o.z = *reinterpret_cast<uint32_t*>(&p2);
    o.w = *reinterpret_cast<uint32_t*>(&p3);
    reinterpret_cast<uint4*>(g_hf)[(size_t)node * 16 + l16] = o;
}

// ---------------- fused final agg + per-graph max readout --------------------
__global__ void __launch_bounds__(256) k_agg_rd(const float* __restrict__ bias,
                                                const int* __restrict__ gids,
                                                float* __restrict__ out, int n) {
    __shared__ int smax[RD_SLOTS * DIMV];
    __shared__ int s_g0;
    int tid = threadIdx.x;
    int n0 = blockIdx.x * 64;
    if (n0 >= n) return;

    for (int i = tid; i < RD_SLOTS * DIMV; i += 256) smax[i] = 0;
    if (tid == 0) s_g0 = gids[n0];
    __syncthreads();
    int g0 = s_g0;

    int l16 = tid & 15;
    int team = tid >> 4;
    const uint4* hw4 = reinterpret_cast<const uint4*>(g_hw);
    float4 bb0 = reinterpret_cast<const float4*>(bias)[l16 * 2];
    float4 bb1 = reinterpret_cast<const float4*>(bias)[l16 * 2 + 1];

    for (int wave = 0; wave < 4; wave++) {
        int node = n0 + wave * 16 + team;
        if (node < n) {
            int beg = g_row_ptr[node];
            int end = g_row_ptr[node + 1];
            float a0 = 0.f, a1 = 0.f, a2 = 0.f, a3 = 0.f;
            float a4 = 0.f, a5 = 0.f, a6 = 0.f, a7 = 0.f;
            int e = beg;
            for (; e + 7 < end; e += 8) {
                int s[8];
#pragma unroll
                for (int j = 0; j < 8; j++) s[j] = g_csr[e + j];
                float nsv[8];
                uint4 v[8];
#pragma unroll
                for (int j = 0; j < 8; j++) { nsv[j] = g_norm_src[s[j]];
                                              v[j] = hw4[(size_t)s[j] * 16 + l16]; }
#pragma unroll
                for (int j = 0; j < 8; j++) {
                    float2 f0 = __half22float2(*reinterpret_cast<__half2*>(&v[j].x));
                    float2 f1 = __half22float2(*reinterpret_cast<__half2*>(&v[j].y));
                    float2 f2 = __half22float2(*reinterpret_cast<__half2*>(&v[j].z));
                    float2 f3 = __half22float2(*reinterpret_cast<__half2*>(&v[j].w));
                    float ns = nsv[j];
                    a0 = fmaf(f0.x, ns, a0); a1 = fmaf(f0.y, ns, a1);
                    a2 = fmaf(f1.x, ns, a2); a3 = fmaf(f1.y, ns, a3);
                    a4 = fmaf(f2.x, ns, a4); a5 = fmaf(f2.y, ns, a5);
                    a6 = fmaf(f3.x, ns, a6); a7 = fmaf(f3.y, ns, a7);
                }
            }
            for (; e < end; ++e) {
                int s = g_csr[e];
                float ns = g_norm_src[s];
                uint4 v = hw4[(size_t)s * 16 + l16];
                float2 f0 = __half22float2(*reinterpret_cast<__half2*>(&v.x));
                float2 f1 = __half22float2(*reinterpret_cast<__half2*>(&v.y));
                float2 f2 = __half22float2(*reinterpret_cast<__half2*>(&v.z));
                float2 f3 = __half22float2(*reinterpret_cast<__half2*>(&v.w));
                a0 = fmaf(f0.x, ns, a0); a1 = fmaf(f0.y, ns, a1);
                a2 = fmaf(f1.x, ns, a2); a3 = fmaf(f1.y, ns, a3);
                a4 = fmaf(f2.x, ns, a4); a5 = fmaf(f2.y, ns, a5);
                a6 = fmaf(f3.x, ns, a6); a7 = fmaf(f3.y, ns, a7);
            }

            float nd = g_norm_dst[node];
            float o[8];
            o[0] = fmaxf(fmaf(a0, nd, bb0.x), 0.f);
            o[1] = fmaxf(fmaf(a1, nd, bb0.y), 0.f);
            o[2] = fmaxf(fmaf(a2, nd, bb0.z), 0.f);
            o[3] = fmaxf(fmaf(a3, nd, bb0.w), 0.f);
            o[4] = fmaxf(fmaf(a4, nd, bb1.x), 0.f);
            o[5] = fmaxf(fmaf(a5, nd, bb1.y), 0.f);
            o[6] = fmaxf(fmaf(a6, nd, bb1.z), 0.f);
            o[7] = fmaxf(fmaf(a7, nd, bb1.w), 0.f);

            int g = gids[node];
            int slot = g - g0;
            if (slot < RD_SLOTS) {
                int base = slot * DIMV + l16 * 8;
#pragma unroll
                for (int k = 0; k < 8; k++)
                    atomicMax(&smax[base + k], __float_as_int(o[k]));
            } else {
#pragma unroll
                for (int k = 0; k < 8; k++)
                    atomicMax(reinterpret_cast<int*>(&out[(size_t)g * DIMV + l16 * 8 + k]),
                              __float_as_int(o[k]));
            }
        }
    }
    __syncthreads();

    for (int i = tid; i < RD_SLOTS * DIMV; i += 256) {
        int v = smax[i];
        if (v != 0) {
            int slot = i >> 7, dim = i & 127;
            atomicMax(reinterpret_cast<int*>(&out[(size_t)(g0 + slot) * DIMV + dim]), v);
        }
    }
}

// ---------------- launch ------------------------------------------------------
extern "C" void kernel_launch(void* const* d_in, const int* in_sizes, int n_in,
                              void* d_out, int out_size) {
    const int*   feat_id = (const int*)  d_in[0];
    const int*   src     = (const int*)  d_in[1];
    const int*   dst     = (const int*)  d_in[2];
    const int*   gids    = (const int*)  d_in[3];
    const float* emb     = (const float*)d_in[4];
    const float* W       = (const float*)d_in[5];
    const float* b       = (const float*)d_in[6];
    float*       out     = (float*)d_out;

    int N = in_sizes[0];
    int E = in_sizes[1];
    int vocab = in_sizes[4] / DIMV;
    if (vocab > MAXV) vocab = MAXV;
    int LAYERS = in_sizes[6] / DIMV;
    if (LAYERS > MAXL) LAYERS = MAXL;

    const int T = 256;
    int nbN   = (N + T - 1) / T;
    int nbE4  = ((E + 3) / 4 + T - 1) / T;
    int nbSc  = (N + SCAN_B - 1) / SCAN_B;
    int nbOut = (out_size + T - 1) / T;
    int nbEmb = (vocab * 32 + T - 1) / T;

    cudaFuncSetAttribute(k_gemm64<0>, cudaFuncAttributeMaxDynamicSharedMemorySize, SM_G64);
    cudaFuncSetAttribute(k_gemm64<1>, cudaFuncAttributeMaxDynamicSharedMemorySize, SM_G64);

    int tiles64 = (N + 63) / 64;
    int aggBlocks = ((N + 1) / 2 + 7) / 8;   // 8 warps/block, 2 nodes/warp

    __half* wt_dev = nullptr;
    cudaGetSymbolAddress((void**)&wt_dev, g_wt);

    cudaStream_t s2 = g_si.s2;

    // fork s2 immediately: its CSR chain has no dependency on main's prep2
    cudaEventRecord(g_si.evA, 0);
    cudaStreamWaitEvent(s2, g_si.evA, 0);

    k_zero_counts<<<nbN, T, 0, s2>>>(N);
    k_hist<<<nbE4, T, 0, s2>>>(src, dst, E);
    k_scanA<<<nbSc, SCAN_B, 0, s2>>>(N);
    k_scanB<<<nbSc, 256, 0, s2>>>(N, E);
    k_fill<<<nbE4, T, 0, s2>>>(src, dst, E);
    cudaEventRecord(g_si.evC, s2);            // CSR + norms ready

    // main: heavy prep (W^T, emb fp16, out zero) then layer-0 GEMM (no CSR dep)
    k_prep2<<<LAYERS + nbOut + nbEmb, T>>>(W, emb, LAYERS, nbOut, out, out_size, vocab);
    k_gemm64<1><<<tiles64, 128, SM_G64>>>(wt_dev, feat_id, N);
    cudaStreamWaitEvent(0, g_si.evC, 0);      // agg needs CSR + norms

    k_agg<<<aggBlocks, 256>>>(b, N);
    for (int l = 1; l < LAYERS; l++) {
        k_gemm64<0><<<tiles64, 128, SM_G64>>>(wt_dev + (size_t)l * DIMV * DIMV, nullptr, N);
        if (l < LAYERS - 1)
            k_agg<<<aggBlocks, 256>>>(b + (size_t)l * DIMV, N);
        else
            k_agg_rd<<<(N + 63) / 64, 256>>>(b + (size_t)l * DIMV, gids, out, N);
    }
}

// round 17
// speedup vs baseline: 1.0600x; 1.0600x over previous
#include <cuda_runtime.h>
#include <cuda_bf16.h>
#include <cuda_fp16.h>
#include <cstdint>

#define MAXN 100000
#define MAXE 1600000
#define DIMV 128
#define SCAN_B 1024
#define MAXL 8
#define ASTH 136           // padded smem stride in halves
#define ASTB 272           // padded smem stride in bytes
#define GRIDP 296          // persistent GEMM grid (2 blocks/SM x 148)
#define RD_SLOTS 16        // per-block graph slots in fused agg+readout

// ---------------- scratch (device globals; no allocation allowed) -------------
__device__ __align__(256) __half g_hf[MAXN * DIMV];         // node features (fp16)
__device__ __align__(256) __half g_hw[MAXN * DIMV];         // h @ W * norm_src (fp16)
__device__ __align__(256) __half g_wt[MAXL * DIMV * DIMV];  // W^T per layer (fp16)
__device__ int    g_csr[MAXE];
__device__ int    g_row_ptr[MAXN + 1];
__device__ int    g_cursor[MAXN];
__device__ int    g_cnt_src[MAXN];
__device__ int    g_cnt_dst[MAXN];
__device__ float  g_norm_dst[MAXN];
__device__ int    g_spine[256];

// ---------------- side stream + events (created at load, before baseline) -----
struct StreamInit {
    cudaStream_t s2;
    cudaEvent_t evA, evB, evC;
    StreamInit() {
        cudaStreamCreateWithFlags(&s2, cudaStreamNonBlocking);
        cudaEventCreateWithFlags(&evA, cudaEventDisableTiming);
        cudaEventCreateWithFlags(&evB, cudaEventDisableTiming);
        cudaEventCreateWithFlags(&evC, cudaEventDisableTiming);
    }
};
static StreamInit g_si;

// ---------------- PTX helpers (base-PTX: ldmatrix/stmatrix/mma/cp.async) ------
__device__ __forceinline__ uint32_t smem_u32(const void* p) {
    uint32_t a;
    asm("{ .reg .u64 t; cvta.to.shared.u64 t, %1; cvt.u32.u64 %0, t; }" : "=r"(a) : "l"(p));
    return a;
}
__device__ __forceinline__ void ldsm_x4(uint32_t& r0, uint32_t& r1, uint32_t& r2,
                                        uint32_t& r3, uint32_t addr) {
    asm volatile("ldmatrix.sync.aligned.m8n8.x4.shared.b16 {%0,%1,%2,%3}, [%4];"
                 : "=r"(r0), "=r"(r1), "=r"(r2), "=r"(r3) : "r"(addr));
}
__device__ __forceinline__ void stsm_x4(uint32_t addr, uint32_t r0, uint32_t r1,
                                        uint32_t r2, uint32_t r3) {
    asm volatile("stmatrix.sync.aligned.m8n8.x4.shared.b16 [%0], {%1,%2,%3,%4};"
                 :: "r"(addr), "r"(r0), "r"(r1), "r"(r2), "r"(r3) : "memory");
}
__device__ __forceinline__ void mma16816(float* c, uint32_t a0, uint32_t a1,
                                         uint32_t a2, uint32_t a3,
                                         uint32_t b0, uint32_t b1) {
    asm volatile("mma.sync.aligned.m16n8k16.row.col.f32.f16.f16.f32 "
                 "{%0,%1,%2,%3}, {%4,%5,%6,%7}, {%8,%9}, {%0,%1,%2,%3};"
                 : "+f"(c[0]), "+f"(c[1]), "+f"(c[2]), "+f"(c[3])
                 : "r"(a0), "r"(a1), "r"(a2), "r"(a3), "r"(b0), "r"(b1));
}
__device__ __forceinline__ void cp16(uint32_t daddr, const void* gaddr, int srcbytes) {
    asm volatile("cp.async.cg.shared.global [%0], [%1], 16, %2;"
                 :: "r"(daddr), "l"(gaddr), "r"(srcbytes) : "memory");
}
__device__ __forceinline__ void cp_commit() {
    asm volatile("cp.async.commit_group;" ::: "memory");
}
__device__ __forceinline__ void cp_wait0() {
    asm volatile("cp.async.wait_group 0;" ::: "memory");
}

// ---------------- prep: zero counters + transpose W + zero out ----------------
__global__ void k_prep(const float* __restrict__ W, int nbN, int n, int layers,
                       float* __restrict__ out, int out_n) {
    int b = blockIdx.x;
    if (b < nbN) {
        int i = b * 256 + threadIdx.x;
        if (i < n) { g_cnt_src[i] = 0; g_cnt_dst[i] = 0; }
    } else if (b < nbN + layers) {
        int l = b - nbN;
        const float* Wl = W + (size_t)l * DIMV * DIMV;
        __half* Wt = g_wt + (size_t)l * DIMV * DIMV;
        for (int i = threadIdx.x; i < DIMV * DIMV; i += 256) {
            int nr = i >> 7, k = i & 127;
            Wt[nr * DIMV + k] = __float2half(Wl[k * DIMV + nr]);
        }
    } else {
        int i = (b - nbN - layers) * 256 + threadIdx.x;
        if (i < out_n) out[i] = 0.0f;
    }
}

// ---------------- degree histograms (4 edges/thread) --------------------------
__global__ void k_hist(const int* __restrict__ src, const int* __restrict__ dst, int E) {
    int q = blockIdx.x * blockDim.x + threadIdx.x;
    int e0 = q * 4;
    if (e0 + 3 < E) {
        int4 s = *reinterpret_cast<const int4*>(src + e0);
        int4 d = *reinterpret_cast<const int4*>(dst + e0);
        atomicAdd(&g_cnt_src[s.x], 1); atomicAdd(&g_cnt_src[s.y], 1);
        atomicAdd(&g_cnt_src[s.z], 1); atomicAdd(&g_cnt_src[s.w], 1);
        atomicAdd(&g_cnt_dst[d.x], 1); atomicAdd(&g_cnt_dst[d.y], 1);
        atomicAdd(&g_cnt_dst[d.z], 1); atomicAdd(&g_cnt_dst[d.w], 1);
    } else {
        for (int e = e0; e < E; ++e) {
            atomicAdd(&g_cnt_src[src[e]], 1);
            atomicAdd(&g_cnt_dst[dst[e]], 1);
        }
    }
}

// ---------------- scan of in-degree counts -> row_ptr (+ norm_dst) ------------
__global__ void k_scan1(int n) {
    __shared__ int s[SCAN_B];
    int i = blockIdx.x * SCAN_B + threadIdx.x;
    int v = (i < n) ? g_cnt_dst[i] : 0;
    if (i < n) g_norm_dst[i] = rsqrtf((float)max(v, 1));
    s[threadIdx.x] = v;
    __syncthreads();
    for (int off = 1; off < SCAN_B; off <<= 1) {
        int t = (threadIdx.x >= off) ? s[threadIdx.x - off] : 0;
        __syncthreads();
        s[threadIdx.x] += t;
        __syncthreads();
    }
    if (i < n) g_row_ptr[i] = s[threadIdx.x] - v;
    if (threadIdx.x == SCAN_B - 1) g_spine[blockIdx.x] = s[SCAN_B - 1];
}

__global__ void k_scan2(int nb) {
    __shared__ int s[SCAN_B];
    int v = (threadIdx.x < nb) ? g_spine[threadIdx.x] : 0;
    s[threadIdx.x] = v;
    __syncthreads();
    for (int off = 1; off < SCAN_B; off <<= 1) {
        int t = (threadIdx.x >= off) ? s[threadIdx.x - off] : 0;
        __syncthreads();
        s[threadIdx.x] += t;
        __syncthreads();
    }
    if (threadIdx.x < nb) g_spine[threadIdx.x] = s[threadIdx.x] - v;
}

__global__ void k_scan3(int n, int E) {
    int i = blockIdx.x * blockDim.x + threadIdx.x;
    if (i < n) {
        int r = g_row_ptr[i] + g_spine[i / SCAN_B];
        g_row_ptr[i] = r;
        g_cursor[i]  = r;
    }
    if (i == 0) g_row_ptr[n] = E;
}

// ---------------- CSR fill (counting sort by dst, 4 edges/thread) -------------
__global__ void k_fill(const int* __restrict__ src, const int* __restrict__ dst, int E) {
    int q = blockIdx.x * blockDim.x + threadIdx.x;
    int e0 = q * 4;
    if (e0 + 3 < E) {
        int4 s = *reinterpret_cast<const int4*>(src + e0);
        int4 d = *reinterpret_cast<const int4*>(dst + e0);
        g_csr[atomicAdd(&g_cursor[d.x], 1)] = s.x;
        g_csr[atomicAdd(&g_cursor[d.y], 1)] = s.y;
        g_csr[atomicAdd(&g_cursor[d.z], 1)] = s.z;
        g_csr[atomicAdd(&g_cursor[d.w], 1)] = s.w;
    } else {
        for (int e = e0; e < E; ++e)
            g_csr[atomicAdd(&g_cursor[dst[e]], 1)] = src[e];
    }
}

// ---------------- embedding gather -> fp16 h ---------------------------------
__global__ void k_embed(const int* __restrict__ feat_id, const float* __restrict__ emb, int n) {
    int idx = blockIdx.x * blockDim.x + threadIdx.x;
    if (idx < n * 16) {
        int node = idx >> 4;
        int c    = idx & 15;
        const float4* e = reinterpret_cast<const float4*>(emb) + (size_t)feat_id[node] * 32 + c * 2;
        float4 a = e[0], b = e[1];
        __half2 h0 = __floats2half2_rn(a.x, a.y);
        __half2 h1 = __floats2half2_rn(a.z, a.w);
        __half2 h2 = __floats2half2_rn(b.x, b.y);
        __half2 h3 = __floats2half2_rn(b.z, b.w);
        uint4 v;
        v.x = *reinterpret_cast<uint32_t*>(&h0);
        v.y = *reinterpret_cast<uint32_t*>(&h1);
        v.z = *reinterpret_cast<uint32_t*>(&h2);
        v.w = *reinterpret_cast<uint32_t*>(&h3);
        reinterpret_cast<uint4*>(g_hf)[idx] = v;
    }
}

// ---------------- persistent HMMA GEMM: hw = norm_src ⊙ (h @ W) --------------
#define SMO_B  0
#define SMO_A0 34816
#define SMO_A1 69632
#define SM_GEMM 104448

__global__ void __launch_bounds__(256) k_gemm_hmma(const __half* __restrict__ Wt,
                                                   int n, int tiles) {
    extern __shared__ char sm[];
    uint32_t sBu  = smem_u32(sm) + SMO_B;
    uint32_t sAu[2] = { smem_u32(sm) + SMO_A0, smem_u32(sm) + SMO_A1 };
    int tid = threadIdx.x, warp = tid >> 5, lane = tid & 31;

    int t0 = blockIdx.x;
    if (t0 >= tiles) return;

    const uint4* Asrc = reinterpret_cast<const uint4*>(g_hf);
    const uint4* Bsrc = reinterpret_cast<const uint4*>(Wt);

    for (int i = tid; i < 2048; i += 256) {
        int r = i >> 4, c = i & 15;
        cp16(sBu + r * ASTB + c * 16, Bsrc + i, 16);
    }
    {
        int row0 = t0 * 128;
        for (int i = tid; i < 2048; i += 256) {
            int r = i >> 4, c = i & 15;
            int gr = row0 + r;
            int ok = (gr < n) ? 16 : 0;
            int grc = (gr < n) ? gr : 0;
            cp16(sAu[0] + r * ASTB + c * 16, Asrc + ((size_t)grc * 16 + c), ok);
        }
    }
    cp_commit();
    cp_wait0();
    __syncthreads();

    int wm = warp >> 1, wn = warp & 1;
    int m0 = wm * 32, nn0 = wn * 64;

    uint32_t a_off = (m0 + (lane & 7) + ((lane & 8) ? 8 : 0)) * ASTB
                   + ((lane & 16) ? 16 : 0);
    uint32_t b_base = sBu + (nn0 + (lane & 7) + ((lane & 16) ? 8 : 0)) * ASTB
                          + ((lane & 8) ? 16 : 0);

    int cur = 0;
    for (int t = t0; t < tiles; t += GRIDP) {
        int row0 = t * 128;
        int tnext = t + GRIDP;

        if (tnext < tiles) {
            int nrow0 = tnext * 128;
            for (int i = tid; i < 2048; i += 256) {
                int r = i >> 4, c = i & 15;
                int gr = nrow0 + r;
                int ok = (gr < n) ? 16 : 0;
                int grc = (gr < n) ? gr : 0;
                cp16(sAu[cur ^ 1] + r * ASTB + c * 16, Asrc + ((size_t)grc * 16 + c), ok);
            }
            cp_commit();
        }

        uint32_t a_base = sAu[cur] + a_off;

        float acc[2][8][4];
#pragma unroll
        for (int mt = 0; mt < 2; mt++)
#pragma unroll
            for (int j = 0; j < 8; j++)
#pragma unroll
                for (int q = 0; q < 4; q++) acc[mt][j][q] = 0.f;

#pragma unroll
        for (int ks = 0; ks < 8; ks++) {
            uint32_t a[2][4];
#pragma unroll
            for (int mt = 0; mt < 2; mt++)
                ldsm_x4(a[mt][0], a[mt][1], a[mt][2], a[mt][3],
                        a_base + mt * 16 * ASTB + ks * 32);
#pragma unroll
            for (int jj = 0; jj < 4; jj++) {
                uint32_t b0, b1, b2, b3;
                ldsm_x4(b0, b1, b2, b3, b_base + jj * 16 * ASTB + ks * 32);
#pragma unroll
                for (int mt = 0; mt < 2; mt++) {
                    mma16816(acc[mt][2 * jj],     a[mt][0], a[mt][1], a[mt][2], a[mt][3], b0, b1);
                    mma16816(acc[mt][2 * jj + 1], a[mt][0], a[mt][1], a[mt][2], a[mt][3], b2, b3);
                }
            }
        }
        __syncthreads();

        float ns0[2], ns1[2];
#pragma unroll
        for (int mt = 0; mt < 2; mt++) {
            int mr0 = row0 + m0 + mt * 16 + (lane >> 2);
            int mr1 = mr0 + 8;
            ns0[mt] = (mr0 < n) ? rsqrtf((float)max(g_cnt_src[mr0], 1)) : 0.f;
            ns1[mt] = (mr1 < n) ? rsqrtf((float)max(g_cnt_src[mr1], 1)) : 0.f;
        }
#pragma unroll
        for (int mt = 0; mt < 2; mt++) {
            uint32_t st_base = sAu[cur]
                + (m0 + mt * 16 + (lane & 7) + ((lane & 8) ? 8 : 0)) * ASTB
                + nn0 * 2 + ((lane & 16) ? 16 : 0);
#pragma unroll
            for (int jj = 0; jj < 4; jj++) {
                __half2 t0lo = __floats2half2_rn(acc[mt][2*jj][0] * ns0[mt],
                                                 acc[mt][2*jj][1] * ns0[mt]);
                __half2 t0hi = __floats2half2_rn(acc[mt][2*jj][2] * ns1[mt],
                                                 acc[mt][2*jj][3] * ns1[mt]);
                __half2 t1lo = __floats2half2_rn(acc[mt][2*jj+1][0] * ns0[mt],
                                                 acc[mt][2*jj+1][1] * ns0[mt]);
                __half2 t1hi = __floats2half2_rn(acc[mt][2*jj+1][2] * ns1[mt],
                                                 acc[mt][2*jj+1][3] * ns1[mt]);
                stsm_x4(st_base + jj * 32,
                        *reinterpret_cast<uint32_t*>(&t0lo),
                        *reinterpret_cast<uint32_t*>(&t0hi),
                        *reinterpret_cast<uint32_t*>(&t1lo),
                        *reinterpret_cast<uint32_t*>(&t1hi));
            }
        }
        __syncthreads();

        char* sAc = sm + (cur ? SMO_A1 : SMO_A0);
        for (int i = tid; i < 2048; i += 256) {
            int r = i >> 4, c = i & 15;
            int gr = row0 + r;
            if (gr < n)
                reinterpret_cast<uint4*>(g_hw)[(size_t)gr * 16 + c] =
                    *reinterpret_cast<uint4*>(sAc + r * ASTB + c * 16);
        }

        if (tnext < tiles) {
            cp_wait0();
            __syncthreads();
        }
        cur ^= 1;
    }
}

// ---------------- edge aggregation (intermediate layers) ----------------------
// half-warp per dst node; lane owns 8 dims (16B fp16 LDG.128), unroll 8.
__global__ void __launch_bounds__(256) k_agg(const float* __restrict__ bias, int n) {
    int gw   = (blockIdx.x * blockDim.x + threadIdx.x) >> 5;
    int lane = threadIdx.x & 31;
    int node = gw * 2 + (lane >> 4);
    int l16  = lane & 15;
    if (node >= n) return;

    int beg = g_row_ptr[node];
    int end = g_row_ptr[node + 1];

    const uint4* hw4 = reinterpret_cast<const uint4*>(g_hw);
    float a0 = 0.f, a1 = 0.f, a2 = 0.f, a3 = 0.f;
    float a4 = 0.f, a5 = 0.f, a6 = 0.f, a7 = 0.f;

    int e = beg;
    for (; e + 7 < end; e += 8) {
        int s[8];
#pragma unroll
        for (int j = 0; j < 8; j++) s[j] = g_csr[e + j];
        uint4 v[8];
#pragma unroll
        for (int j = 0; j < 8; j++) v[j] = hw4[(size_t)s[j] * 16 + l16];
#pragma unroll
        for (int j = 0; j < 8; j++) {
            float2 f0 = __half22float2(*reinterpret_cast<__half2*>(&v[j].x));
            float2 f1 = __half22float2(*reinterpret_cast<__half2*>(&v[j].y));
            float2 f2 = __half22float2(*reinterpret_cast<__half2*>(&v[j].z));
            float2 f3 = __half22float2(*reinterpret_cast<__half2*>(&v[j].w));
            a0 += f0.x; a1 += f0.y; a2 += f1.x; a3 += f1.y;
            a4 += f2.x; a5 += f2.y; a6 += f3.x; a7 += f3.y;
        }
    }
    for (; e < end; ++e) {
        uint4 v = hw4[(size_t)g_csr[e] * 16 + l16];
        float2 f0 = __half22float2(*reinterpret_cast<__half2*>(&v.x));
        float2 f1 = __half22float2(*reinterpret_cast<__half2*>(&v.y));
        float2 f2 = __half22float2(*reinterpret_cast<__half2*>(&v.z));
        float2 f3 = __half22float2(*reinterpret_cast<__half2*>(&v.w));
        a0 += f0.x; a1 += f0.y; a2 += f1.x; a3 += f1.y;
        a4 += f2.x; a5 += f2.y; a6 += f3.x; a7 += f3.y;
    }

    float nd = g_norm_dst[node];
    float4 bb0 = reinterpret_cast<const float4*>(bias)[l16 * 2];
    float4 bb1 = reinterpret_cast<const float4*>(bias)[l16 * 2 + 1];
    __half2 p0 = __floats2half2_rn(fmaxf(fmaf(a0, nd, bb0.x), 0.f),
                                   fmaxf(fmaf(a1, nd, bb0.y), 0.f));
    __half2 p1 = __floats2half2_rn(fmaxf(fmaf(a2, nd, bb0.z), 0.f),
                                   fmaxf(fmaf(a3, nd, bb0.w), 0.f));
    __half2 p2 = __floats2half2_rn(fmaxf(fmaf(a4, nd, bb1.x), 0.f),
                                   fmaxf(fmaf(a5, nd, bb1.y), 0.f));
    __half2 p3 = __floats2half2_rn(fmaxf(fmaf(a6, nd, bb1.z), 0.f),
                                   fmaxf(fmaf(a7, nd, bb1.w), 0.f));
    uint4 o;
    o.x = *reinterpret_cast<uint32_t*>(&p0);
    o.y = *reinterpret_cast<uint32_t*>(&p1);
    o.z = *reinterpret_cast<uint32_t*>(&p2);
    o.w = *reinterpret_cast<uint32_t*>(&p3);
    reinterpret_cast<uint4*>(g_hf)[(size_t)node * 16 + l16] = o;
}

// ---------------- fused final agg + per-graph max readout --------------------
__global__ void __launch_bounds__(256) k_agg_rd(const float* __restrict__ bias,
                                                const int* __restrict__ gids,
                                                float* __restrict__ out, int n) {
    __shared__ int smax[RD_SLOTS * DIMV];
    __shared__ int s_g0;
    int tid = threadIdx.x;
    int n0 = blockIdx.x * 64;
    if (n0 >= n) return;

    for (int i = tid; i < RD_SLOTS * DIMV; i += 256) smax[i] = 0;
    if (tid == 0) s_g0 = gids[n0];
    __syncthreads();
    int g0 = s_g0;

    int l16 = tid & 15;
    int team = tid >> 4;
    const uint4* hw4 = reinterpret_cast<const uint4*>(g_hw);
    float4 bb0 = reinterpret_cast<const float4*>(bias)[l16 * 2];
    float4 bb1 = reinterpret_cast<const float4*>(bias)[l16 * 2 + 1];

    for (int wave = 0; wave < 4; wave++) {
        int node = n0 + wave * 16 + team;
        if (node < n) {
            int beg = g_row_ptr[node];
            int end = g_row_ptr[node + 1];
            float a0 = 0.f, a1 = 0.f, a2 = 0.f, a3 = 0.f;
            float a4 = 0.f, a5 = 0.f, a6 = 0.f, a7 = 0.f;
            int e = beg;
            for (; e + 7 < end; e += 8) {
                int s[8];
#pragma unroll
                for (int j = 0; j < 8; j++) s[j] = g_csr[e + j];
                uint4 v[8];
#pragma unroll
                for (int j = 0; j < 8; j++) v[j] = hw4[(size_t)s[j] * 16 + l16];
#pragma unroll
                for (int j = 0; j < 8; j++) {
                    float2 f0 = __half22float2(*reinterpret_cast<__half2*>(&v[j].x));
                    float2 f1 = __half22float2(*reinterpret_cast<__half2*>(&v[j].y));
                    float2 f2 = __half22float2(*reinterpret_cast<__half2*>(&v[j].z));
                    float2 f3 = __half22float2(*reinterpret_cast<__half2*>(&v[j].w));
                    a0 += f0.x; a1 += f0.y; a2 += f1.x; a3 += f1.y;
                    a4 += f2.x; a5 += f2.y; a6 += f3.x; a7 += f3.y;
                }
            }
            for (; e < end; ++e) {
                uint4 v = hw4[(size_t)g_csr[e] * 16 + l16];
                float2 f0 = __half22float2(*reinterpret_cast<__half2*>(&v.x));
                float2 f1 = __half22float2(*reinterpret_cast<__half2*>(&v.y));
                float2 f2 = __half22float2(*reinterpret_cast<__half2*>(&v.z));
                float2 f3 = __half22float2(*reinterpret_cast<__half2*>(&v.w));
                a0 += f0.x; a1 += f0.y; a2 += f1.x; a3 += f1.y;
                a4 += f2.x; a5 += f2.y; a6 += f3.x; a7 += f3.y;
            }

            float nd = g_norm_dst[node];
            float o[8];
            o[0] = fmaxf(fmaf(a0, nd, bb0.x), 0.f);
            o[1] = fmaxf(fmaf(a1, nd, bb0.y), 0.f);
            o[2] = fmaxf(fmaf(a2, nd, bb0.z), 0.f);
            o[3] = fmaxf(fmaf(a3, nd, bb0.w), 0.f);
            o[4] = fmaxf(fmaf(a4, nd, bb1.x), 0.f);
            o[5] = fmaxf(fmaf(a5, nd, bb1.y), 0.f);
            o[6] = fmaxf(fmaf(a6, nd, bb1.z), 0.f);
            o[7] = fmaxf(fmaf(a7, nd, bb1.w), 0.f);

            int g = gids[node];
            int slot = g - g0;
            if (slot < RD_SLOTS) {
                int base = slot * DIMV + l16 * 8;
#pragma unroll
                for (int k = 0; k < 8; k++)
                    atomicMax(&smax[base + k], __float_as_int(o[k]));
            } else {
#pragma unroll
                for (int k = 0; k < 8; k++)
                    atomicMax(reinterpret_cast<int*>(&out[(size_t)g * DIMV + l16 * 8 + k]),
                              __float_as_int(o[k]));
            }
        }
    }
    __syncthreads();

    for (int i = tid; i < RD_SLOTS * DIMV; i += 256) {
        int v = smax[i];
        if (v != 0) {
            int slot = i >> 7, dim = i & 127;
            atomicMax(reinterpret_cast<int*>(&out[(size_t)(g0 + slot) * DIMV + dim]), v);
        }
    }
}

// ---------------- launch ------------------------------------------------------
extern "C" void kernel_launch(void* const* d_in, const int* in_sizes, int n_in,
                              void* d_out, int out_size) {
    const int*   feat_id = (const int*)  d_in[0];
    const int*   src     = (const int*)  d_in[1];
    const int*   dst     = (const int*)  d_in[2];
    const int*   gids    = (const int*)  d_in[3];
    const float* emb     = (const float*)d_in[4];
    const float* W       = (const float*)d_in[5];
    const float* b       = (const float*)d_in[6];
    float*       out     = (float*)d_out;

    int N = in_sizes[0];
    int E = in_sizes[1];
    int LAYERS = in_sizes[6] / DIMV;
    if (LAYERS > MAXL) LAYERS = MAXL;

    const int T = 256;
    int nbN   = (N + T - 1) / T;
    int nbE4  = ((E + 3) / 4 + T - 1) / T;
    int nbSc  = (N + SCAN_B - 1) / SCAN_B;
    int nbOut = (out_size + T - 1) / T;

    cudaFuncSetAttribute(k_gemm_hmma, cudaFuncAttributeMaxDynamicSharedMemorySize, SM_GEMM);

    int tiles = (N + 127) / 128;
    int gemmGrid = (tiles < GRIDP) ? tiles : GRIDP;
    int aggBlocks = ((N + 1) / 2 + 7) / 8;   // 8 warps/block, 2 nodes/warp

    __half* wt_dev = nullptr;
    cudaGetSymbolAddress((void**)&wt_dev, g_wt);

    cudaStream_t s2 = g_si.s2;

    // --- main stream (0): prep -> embed -> gemm chain
    // --- side stream   : CSR build (hist -> scans -> fill), forked after prep
    k_prep<<<nbN + LAYERS + nbOut, T>>>(W, nbN, N, LAYERS, out, out_size);
    cudaEventRecord(g_si.evA, 0);
    cudaStreamWaitEvent(s2, g_si.evA, 0);

    k_hist<<<nbE4, T, 0, s2>>>(src, dst, E);
    cudaEventRecord(g_si.evB, s2);           // cnt_src/cnt_dst ready
    k_scan1<<<nbSc, SCAN_B, 0, s2>>>(N);
    k_scan2<<<1, SCAN_B, 0, s2>>>(nbSc);
    k_scan3<<<nbN, T, 0, s2>>>(N, E);
    k_fill<<<nbE4, T, 0, s2>>>(src, dst, E);
    cudaEventRecord(g_si.evC, s2);           // CSR ready

    k_embed<<<(N * 16 + T - 1) / T, T>>>(feat_id, emb, N);
    cudaStreamWaitEvent(0, g_si.evB, 0);     // gemm epilogue needs cnt_src
    k_gemm_hmma<<<gemmGrid, 256, SM_GEMM>>>(wt_dev, N, tiles);
    cudaStreamWaitEvent(0, g_si.evC, 0);     // agg needs CSR

    k_agg<<<aggBlocks, 256>>>(b, N);
    for (int l = 1; l < LAYERS; l++) {
        k_gemm_hmma<<<gemmGrid, 256, SM_GEMM>>>(wt_dev + (size_t)l * DIMV * DIMV, N, tiles);
        if (l < LAYERS - 1)
            k_agg<<<aggBlocks, 256>>>(b + (size_t)l * DIMV, N);
        else
            k_agg_rd<<<(N + 63) / 64, 256>>>(b + (size_t)l * DIMV, gids, out, N);
    }
}